// round 10
// baseline (speedup 1.0000x reference)
#include <cuda_runtime.h>
#include <stdint.h>

// samx_qkv_1bit: suffix-automaton retrieval, 1024 independent serial rows.
// R10 = R9 (register-resident chain, warp-cooperative key side) + OVERLAP:
//   lane 0 runs the serial query while lanes 1-31 run the entire register-only
//   key machinery (mask 0xFFFFFFFE). Enabled by: tk[g] provably absent (lane 0
//   never in ballots); recd derived without plant-wait (d==g -> grec register,
//   d on chain -> shfl of planted copy, else S[d] untouched); images provably
//   never plant-targets. All S stores batched post-query; 2 syncwarps/step
//   (3 on clone steps, preserving R9's redirect->image ordering).
// smem/block: 229376 (records) + 1792 (vpk) = 231168.

#define BB 4
#define TT 2048
#define CC 256
#define NROWS (BB*CC)          // 1024
#define WPB (TT/32)            // 64 packed words per row
#define STATES 4096            // SAM has <= 2n-1 = 4095 states
#define RPB 7                  // rows (warps) per block

typedef unsigned long long ull;
#define IDA 0xFFF              // 12-bit absent / -1 marker
#define F_SH 24
#define M_SH 36
#define R_SH 48
#define FULLM 0xFFFFFFFFu
#define M31   0xFFFFFFFEu
#define RMASK (0xFFFFull << R_SH)
#define MMASK ((ull)IDA << M_SH)
#define FMASK ((ull)IDA << F_SH)

__device__ uint32_t g_qpack[NROWS*WPB];
__device__ uint32_t g_kpack[NROWS*WPB];
__device__ uint32_t g_vpack[NROWS*WPB];

// ---------------------------------------------------------------------------
__global__ void samx_pack_kernel(const float* __restrict__ q,
                                 const float* __restrict__ k,
                                 const float* __restrict__ v) {
    int c  = threadIdx.x;
    int wi = blockIdx.x;
    int b  = blockIdx.y;
    int row = b * CC + c;
    size_t base = ((size_t)b * TT + (size_t)wi * 32) * CC + c;
    uint32_t qw = 0, kw = 0, vw = 0;
#pragma unroll
    for (int s = 0; s < 32; s++) {
        if (q[base + (size_t)s * CC] > 0.f) qw |= 1u << s;
        if (k[base + (size_t)s * CC] > 0.f) kw |= 1u << s;
        if (v[base + (size_t)s * CC] > 0.f) vw |= 1u << s;
    }
    g_qpack[row * WPB + wi] = qw;
    g_kpack[row * WPB + wi] = kw;
    g_vpack[row * WPB + wi] = vw;
}

// ---------------------------------------------------------------------------
extern "C" __global__ void __launch_bounds__(32*RPB, 1)
samx_sam_kernel(const float* __restrict__ e, float* __restrict__ out) {
    extern __shared__ ull smem[];
    int warp = threadIdx.x >> 5;
    int lane = threadIdx.x & 31;
    int row  = blockIdx.x * RPB + warp;

    ull* S = smem + (size_t)warp * STATES;
    unsigned short* Sr = (unsigned short*)S;              // r+1 halfword = idx 4n+3
    uint32_t* vpk_s = (uint32_t*)(smem + (size_t)RPB * STATES) + warp * WPB;

    if (row < NROWS) {
        vpk_s[lane]      = g_vpack[row * WPB + lane];
        vpk_s[lane + 32] = g_vpack[row * WPB + lane + 32];
    }
    __syncwarp();
    if (row >= NROWS) return;

    const uint32_t* qpk = g_qpack + row * WPB;
    const uint32_t* kpk = g_kpack + row * WPB;

    int b = row >> 8;
    int c = row & (CC - 1);
    float ev = e[c];
    float* op = out + (size_t)b * TT * CC + c;

    // ---- bootstrap: step i=0 done inline ----
    uint32_t qw, kw;
    { uint32_t a = 0, b2 = 0;
      if (lane == 0) { a = qpk[0]; b2 = kpk[0]; }
      qw = __shfl_sync(FULLM, a, 0); kw = __shfl_sync(FULLM, b2, 0); }
    int k0 = (kw & 1) ? 12 : 0;
    ull rootrec = (ull)IDA | ((ull)IDA << 12) | ((ull)IDA << F_SH);
    ull rootP = (rootrec & ~((ull)IDA << k0)) | ((ull)1 << k0);  // tk[root]=1
    // node 1: tr absent, f=0, m=1, r+1=1
    ull grec = (ull)IDA | ((ull)IDA << 12) | ((ull)1 << M_SH) | ((ull)1 << R_SH);
    if (lane == 0) { S[0] = rootP; S[1] = grec; op[0] = -ev; }  // query(0): y=0
    ull myrec = (lane == 0) ? grec : rootP;
    int myid  = (lane == 0) ? 1 : 0;
    int L = 2, g = 1, u = 2, w = 0, h = 0;
    bool degraded = false;
    __syncwarp();

    for (int i = 1; i < TT; i++) {
        if ((i & 31) == 0) {
            uint32_t a = 0, b2 = 0;
            if (lane == 0) { int wi = i >> 5; a = qpk[wi]; b2 = kpk[wi]; }
            qw = __shfl_sync(FULLM, a, 0); kw = __shfl_sync(FULLM, b2, 0);
        }
        int qs = ((qw >> (i & 31)) & 1) ? 12 : 0;
        int ks = ((kw >> (i & 31)) & 1) ? 12 : 0;
        int j = u;
        ull rvR = ((ull)(i + 1)) << R_SH;
        unsigned short rv = (unsigned short)(i + 1);

        if (!degraded) {
            int t = lane;
            bool validt = (t < L);
            // register-phase outputs (lanes 1-31; lane 0 keeps defaults)
            int tkt = IDA, s_ = 0, srcsel = 0, idA = 0;
            ull planted = 0, recd = 0, fjrec = 0, redirected = 0;
            ull recA = 0, recRootN = 0;
            int tgt = 0;
            bool inrun_ = false;
            unsigned packed = 0;

            if (lane == 0) {
                // ---- query: serial walk (reads S only) ----
                int p = w, x = h;
                for (;;) {
                    if (p < 0) { p = 0; x = 0; break; }
                    ull rec = S[p];
                    int tq = (int)((rec >> qs) & IDA);
                    if (tq != IDA) { p = tq; x += 1; break; }
                    int mp = (int)((rec >> M_SH) & IDA);
                    if (x > mp) x = mp;
                    int f = (int)((rec >> F_SH) & IDA);
                    p = (f == IDA) ? -1 : f;
                }
                int y = 0;
                if (x > 0) {
                    ull recv = S[p];
                    for (;;) {
                        int f = (int)((recv >> F_SH) & IDA);
                        if (f == IDA) break;
                        ull recf = S[f];
                        if ((int)((recf >> M_SH) & IDA) >= x) recv = recf;
                        else break;
                    }
                    int idx = (int)(recv >> R_SH);
                    y = (int)((vpk_s[idx >> 5] >> (idx & 31)) & 1u);
                }
                op[(size_t)i * CC] = y ? ev : -ev;
                w = p; h = x;
            } else {
                // ---- register-only key machinery (mask M31) ----
                tkt = validt ? (int)((myrec >> ks) & IDA) : IDA;
                int mpt = (int)((myrec >> M_SH) & IDA);
                planted = (myrec & ~((ull)IDA << ks)) | ((ull)j << ks);
                unsigned pres = __ballot_sync(M31, tkt != IDA);
                if (pres) {
                    s_ = __ffs(pres) - 1;                // >= 1 (tk[g] absent)
                    int d_  = __shfl_sync(M31, tkt, s_);
                    int mp_ = __shfl_sync(M31, mpt, s_);
                    unsigned dch = __ballot_sync(M31, validt && (t < s_) && (myid == d_));
                    if (d_ == g)      recd = (grec & ~((ull)IDA << ks)) | ((ull)j << ks);
                    else if (dch)     recd = __shfl_sync(M31, planted, __ffs(dch) - 1);
                    else              recd = S[d_];      // off-chain: untouched
                    int md = (int)((recd >> M_SH) & IDA);
                    bool clone_ = (mp_ + 1 != md);
                    int bc = j + 1;
                    int fj_ = clone_ ? bc : d_;
                    fjrec = clone_
                        ? ((recd & ~(MMASK | RMASK)) | ((ull)(mp_ + 1) << M_SH) | rvR)
                        : ((recd & ~RMASK) | rvR);
                    bool hitd = validt && (tkt == d_);
                    inrun_ = (t > s_) && hitd;
                    redirected = (myrec & ~((ull)IDA << ks)) | ((ull)bc << ks);
                    ull updrec = (t < s_) ? planted
                               : ((clone_ && hitd) ? redirected : myrec);
                    tgt = (clone_ && inrun_) ? bc : tkt;
                    if (t == s_) tgt = fj_;
                    int prevtgt = __shfl_up_sync(M31, tgt, 1);
                    bool keep = validt && (t > s_) && (tgt != prevtgt);
                    unsigned keepm = __ballot_sync(M31, keep);
                    int nk_ = __popc(keepm);
                    {   // srcsel = position of (t-1)-th set bit of keepm
                        int o = t - 1;
                        unsigned m2 = keepm; int sp = 0, cth;
                        cth = __popc(m2 & 0xFFFFu); if (o > cth) { sp += 16; o -= cth; m2 >>= 16; }
                        cth = __popc(m2 & 0xFFu);   if (o > cth) { sp += 8;  o -= cth; m2 >>= 8; }
                        cth = __popc(m2 & 0xFu);    if (o > cth) { sp += 4;  o -= cth; m2 >>= 4; }
                        cth = __popc(m2 & 0x3u);    if (o > cth) { sp += 2;  o -= cth; m2 >>= 2; }
                        cth = (int)(m2 & 1u);       if (o > cth) { sp += 1; }
                        srcsel = sp;
                    }
                    idA = __shfl_sync(M31, tgt, srcsel);
                    recRootN = __shfl_sync(M31, updrec, L - 1);
                    if (!clone_) {
                        // images provably not plant-targets: safe early loads
                        bool vimg = validt && (t > s_) && !inrun_;
                        ull imgrec = S[vimg ? tkt : 0];
                        ull imgP = (imgrec & ~RMASK) | rvR;
                        recA = __shfl_sync(M31, imgP, srcsel);
                    }
                    packed = 1u | (clone_ ? 2u : 0u)
                           | ((unsigned)fj_ << 2) | ((unsigned)nk_ << 14)
                           | ((unsigned)d_ << 20);
                } else {
                    recRootN = __shfl_sync(M31, planted, L - 1);
                    packed = 0;
                }
            }
            __syncwarp();   // query done; register results ready
            unsigned pk = __shfl_sync(FULLM, packed, 1);
            bool present = pk & 1u;
            bool clone   = (pk >> 1) & 1u;
            int fj = (int)((pk >> 2) & IDA);
            int nk = (int)((pk >> 14) & 63u);
            int dd = (int)((pk >> 20) & IDA);
            ull jrec = (ull)IDA | ((ull)IDA << 12) | ((ull)fj << F_SH)
                     | ((ull)(i + 1) << M_SH) | rvR;
            int Lnext;

            if (!present) {
                if (lane == 0) {
                    ull pl = (grec & ~((ull)IDA << ks)) | ((ull)j << ks);
                    S[g] = pl; S[j] = jrec;
                    myrec = jrec; myid = j;
                } else {
                    if (validt) S[myid] = planted;
                    myrec = recRootN; myid = 0;
                }
                Lnext = 2;
            } else if (!clone) {
                if (lane == 0) {
                    ull pl = (grec & ~((ull)IDA << ks)) | ((ull)j << ks);
                    if (dd == g) pl = (pl & ~RMASK) | rvR;   // g==fj gets r=rv
                    S[g] = pl; S[j] = jrec;
                    myrec = jrec; myid = j;
                } else {
                    if (t < s_) {
                        ull pl = (myid == dd) ? ((planted & ~RMASK) | rvR) : planted;
                        S[myid] = pl;
                    }
                    if (t == s_) Sr[(dd << 2) | 3] = rv;     // dup-benign
                    if (validt && t > s_) Sr[(tgt << 2) | 3] = rv;
                    if (t == 1)            { myrec = fjrec; myid = fj; }
                    else if (t < 2 + nk)   { myrec = recA;  myid = idA; }
                    else                   { myrec = recRootN; myid = 0; }
                }
                Lnext = nk + 3;
            } else {
                int bc = j + 1;
                // stores round 1: plants + clone trio + redirects
                if (lane == 0) {
                    if (dd != g) {   // if dd==g, lane s_'s S[dd] carries the plant
                        ull pl = (grec & ~((ull)IDA << ks)) | ((ull)j << ks);
                        S[g] = pl;
                    }
                } else {
                    if (t < s_ && myid != dd) S[myid] = planted;
                    if (t == s_) {
                        S[myid] = redirected;
                        S[dd] = (recd & ~FMASK) | ((ull)bc << F_SH);
                        S[bc] = fjrec;
                    } else if (validt && inrun_) {
                        S[myid] = redirected;
                    }
                }
                __syncwarp();   // redirects visible before image loads (case-a)
                bool vimg = (lane != 0) && validt && (t > s_) && !inrun_;
                ull imgrec = S[vimg ? tkt : 0];
                ull imgP = (imgrec & ~RMASK) | rvR;
                if (lane != 0 && validt && t > s_) Sr[(tgt << 2) | 3] = rv;
                recA = __shfl_sync(FULLM, imgP, srcsel);
                if (lane == 0) {
                    S[j] = jrec;
                    myrec = jrec; myid = j;
                } else {
                    if (t == 1)            { myrec = fjrec; myid = fj; }
                    else if (t < 2 + nk)   { myrec = recA;  myid = idA; }
                    else                   { myrec = recRootN; myid = 0; }
                }
                Lnext = nk + 3;
            }
            g = j; grec = jrec;
            u += clone ? 2 : 1;
            L = Lnext;
            if (L > 32) degraded = true;   // S coherent; fallback takes over
        } else {
            // ---- serial fallback: reference-style dependent walks ----
            if (lane == 0) {
                int fj;
                int p2 = g;
                for (;;) {
                    if (p2 < 0) { fj = 0; break; }
                    ull t2r = S[p2];
                    int tk = (int)((t2r >> ks) & IDA);
                    if (tk == IDA) {
                        S[p2] = (t2r & ~((ull)IDA << ks)) | ((ull)j << ks);
                        int f = (int)((t2r >> F_SH) & IDA);
                        p2 = (f == IDA) ? -1 : f;
                    } else {
                        int d = tk;
                        ull recd = S[d];
                        int md = (int)((recd >> M_SH) & IDA);
                        int mp = (int)((t2r >> M_SH) & IDA);
                        if (mp + 1 == md) {
                            fj = d;
                        } else {
                            int bc = j + 1;
                            S[bc] = (recd & ~MMASK) | ((ull)(mp + 1) << M_SH);
                            S[d]  = (recd & ~FMASK) | ((ull)bc << F_SH);
                            fj = bc;
                            u += 1;
                            for (;;) {
                                ull t3 = S[p2];
                                if (((t3 >> ks) & IDA) != (ull)d) break;
                                S[p2] = (t3 & ~((ull)IDA << ks)) | ((ull)bc << ks);
                                int f = (int)((t3 >> F_SH) & IDA);
                                if (f == IDA) break;
                                p2 = f;
                            }
                        }
                        break;
                    }
                }
                int vst = fj;
                while (vst != 0) {
                    ull rc = S[vst];
                    Sr[(vst << 2) | 3] = rv;
                    int f = (int)((rc >> F_SH) & IDA);
                    if (f == IDA) break;
                    vst = f;
                }
                S[j] = (ull)IDA | ((ull)IDA << 12)
                     | ((ull)fj << F_SH)
                     | ((ull)(i + 1) << M_SH) | rvR;
                g = j;
                u += 1;
            }
            // also run the query on lane 0 (was skipped above in degraded mode)
            // NOTE: degraded branch order: query FIRST, then key — done below.
            g = __shfl_sync(FULLM, g, 0);
            u = __shfl_sync(FULLM, u, 0);
        }
        __syncwarp();   // all key writes visible to next step
    }
}

extern "C" void kernel_launch(void* const* d_in, const int* in_sizes, int n_in,
                              void* d_out, int out_size) {
    const float* q = (const float*)d_in[0];
    const float* k = (const float*)d_in[1];
    const float* v = (const float*)d_in[2];
    const float* e = (const float*)d_in[3];
    float* out = (float*)d_out;

    dim3 pg(WPB, BB);
    samx_pack_kernel<<<pg, CC>>>(q, k, v);

    size_t smem = (size_t)RPB * STATES * sizeof(ull)
                + (size_t)RPB * WPB * sizeof(uint32_t);   // 231168
    cudaFuncSetAttribute(samx_sam_kernel,
                         cudaFuncAttributeMaxDynamicSharedMemorySize, (int)smem);
    int blocks = (NROWS + RPB - 1) / RPB;                 // 147
    samx_sam_kernel<<<blocks, 32 * RPB, smem>>>(e, out);
}

// round 11
// speedup vs baseline: 1.5582x; 1.5582x over previous
#include <cuda_runtime.h>
#include <stdint.h>

// samx_qkv_1bit: suffix-automaton retrieval, 1024 independent serial rows.
// R11: fully UNIFORM warp-cooperative step (R10's divergent overlap reverted).
//  - query runs redundantly on all 32 lanes (broadcast LDS, zero divergence),
//    interleaving with the key side's independent collective chain
//  - chain records RELOADED per step from S via a 34-entry smem id array
//    (kills R9's 170-cyc dedup shuffle tail and all carry-coherence hazards)
//  - image loads eliminated (ids register-known; r-propagation = STS.16)
//  - recd derived pre-store-phase (on-chain -> shfl of planted copy, else
//    early S[d] load overlapping the query); ONE store phase; 3 syncs/step
// smem/block: 229376 (records) + 1792 (vpk) + 476 (NCid) = 231644 <= 232448.

#define BB 4
#define TT 2048
#define CC 256
#define NROWS (BB*CC)          // 1024
#define WPB (TT/32)            // 64 packed words per row
#define STATES 4096            // SAM has <= 2n-1 = 4095 states
#define RPB 7                  // rows (warps) per block
#define CAPC 34                // NCid slots per warp

typedef unsigned long long ull;
#define IDA 0xFFF              // 12-bit absent / -1 marker
#define F_SH 24
#define M_SH 36
#define R_SH 48
#define FULLM 0xFFFFFFFFu
#define RMASK (0xFFFFull << R_SH)
#define MMASK ((ull)IDA << M_SH)
#define FMASK ((ull)IDA << F_SH)

__device__ uint32_t g_qpack[NROWS*WPB];
__device__ uint32_t g_kpack[NROWS*WPB];
__device__ uint32_t g_vpack[NROWS*WPB];

// ---------------------------------------------------------------------------
__global__ void samx_pack_kernel(const float* __restrict__ q,
                                 const float* __restrict__ k,
                                 const float* __restrict__ v) {
    int c  = threadIdx.x;
    int wi = blockIdx.x;
    int b  = blockIdx.y;
    int row = b * CC + c;
    size_t base = ((size_t)b * TT + (size_t)wi * 32) * CC + c;
    uint32_t qw = 0, kw = 0, vw = 0;
#pragma unroll
    for (int s = 0; s < 32; s++) {
        if (q[base + (size_t)s * CC] > 0.f) qw |= 1u << s;
        if (k[base + (size_t)s * CC] > 0.f) kw |= 1u << s;
        if (v[base + (size_t)s * CC] > 0.f) vw |= 1u << s;
    }
    g_qpack[row * WPB + wi] = qw;
    g_kpack[row * WPB + wi] = kw;
    g_vpack[row * WPB + wi] = vw;
}

// ---------------------------------------------------------------------------
extern "C" __global__ void __launch_bounds__(32*RPB, 1)
samx_sam_kernel(const float* __restrict__ e, float* __restrict__ out) {
    extern __shared__ ull smem[];
    int warp = threadIdx.x >> 5;
    int lane = threadIdx.x & 31;
    int row  = blockIdx.x * RPB + warp;

    ull* S = smem + (size_t)warp * STATES;
    unsigned short* Sr = (unsigned short*)S;              // r+1 halfword = idx 4n+3
    uint32_t* vpk_s = (uint32_t*)(smem + (size_t)RPB * STATES) + warp * WPB;
    unsigned short* NC = (unsigned short*)((char*)smem
                       + (size_t)RPB * STATES * sizeof(ull)
                       + (size_t)RPB * WPB * sizeof(uint32_t))
                       + warp * CAPC;

    if (row < NROWS) {
        vpk_s[lane]      = g_vpack[row * WPB + lane];
        vpk_s[lane + 32] = g_vpack[row * WPB + lane + 32];
    }
    __syncwarp();
    if (row >= NROWS) return;

    const uint32_t* qpk = g_qpack + row * WPB;
    const uint32_t* kpk = g_kpack + row * WPB;

    int b = row >> 8;
    int c = row & (CC - 1);
    float ev = e[c];
    float* op = out + (size_t)b * TT * CC + c;

    // ---- bootstrap: step i=0 inline ----
    uint32_t qw, kw;
    { uint32_t a = 0, b2 = 0;
      if (lane == 0) { a = qpk[0]; b2 = kpk[0]; }
      qw = __shfl_sync(FULLM, a, 0); kw = __shfl_sync(FULLM, b2, 0); }
    int k0 = (kw & 1) ? 12 : 0;
    ull rootP = ((ull)IDA | ((ull)IDA << 12) | ((ull)IDA << F_SH));
    rootP = (rootP & ~((ull)IDA << k0)) | ((ull)1 << k0);   // tk[root]=1
    ull n1 = (ull)IDA | ((ull)IDA << 12) | ((ull)1 << M_SH) | ((ull)1 << R_SH);
    if (lane == 0) {
        S[0] = rootP; S[1] = n1;
        NC[0] = 1; NC[1] = 0;
        op[0] = -ev;                                        // query(0): y=0
    }
    int L = 2, g = 1, u = 2, w = 0, h = 0;
    bool degraded = false;
    __syncwarp();

    for (int i = 1; i < TT; i++) {
        if ((i & 31) == 0) {
            uint32_t a = 0, b2 = 0;
            if (lane == 0) { int wi = i >> 5; a = qpk[wi]; b2 = kpk[wi]; }
            qw = __shfl_sync(FULLM, a, 0); kw = __shfl_sync(FULLM, b2, 0);
        }
        int qs = ((qw >> (i & 31)) & 1) ? 12 : 0;
        int ks = ((kw >> (i & 31)) & 1) ? 12 : 0;
        int j = u;
        ull rvR = ((ull)(i + 1)) << R_SH;
        unsigned short rv = (unsigned short)(i + 1);

        if (!degraded) {
            // ---- register/collective phase (uniform, no S writes) ----
            int idt = (int)NC[lane] & IDA;
            ull rec = S[idt];
            bool validt = (lane < L);
            int tkt = validt ? (int)((rec >> ks) & IDA) : IDA;
            int mpt = (int)((rec >> M_SH) & IDA);
            ull planted = (rec & ~((ull)IDA << ks)) | ((ull)j << ks);
            unsigned pres = __ballot_sync(FULLM, tkt != IDA);
            int s = pres ? (__ffs(pres) - 1) : L;
            int d  = __shfl_sync(FULLM, tkt, s & 31);
            int mp = __shfl_sync(FULLM, mpt, s & 31);
            unsigned dch = __ballot_sync(FULLM, validt && (lane < s) && (idt == d));
            bool donchain = pres && (dch != 0);
            int dlane = (__ffs(dch) - 1) & 31;
            ull recd_l = S[pres ? d : 0];                 // early, overlaps query
            ull plsh = __shfl_sync(FULLM, planted, dlane);
            ull recd = donchain ? plsh : recd_l;
            int md = (int)((recd >> M_SH) & IDA);
            bool clone = pres && (mp + 1 != md);
            int bc = j + 1;
            int fj = pres ? (clone ? bc : d) : 0;
            bool hitd = validt && (tkt == d);
            bool inrun = (lane > s) && hitd;
            int tgt = (clone && inrun) ? bc : tkt;
            if (lane == s) tgt = fj;
            int prevtgt = __shfl_up_sync(FULLM, tgt, 1);
            bool keep = validt && (lane > s) && (tgt != prevtgt);
            unsigned keepm = __ballot_sync(FULLM, keep);
            int nk = __popc(keepm);
            int pos = 2 + __popc(keepm & ((1u << lane) - 1u));
            int Lnext = pres ? nk + 3 : 2;
            ull jrec = (ull)IDA | ((ull)IDA << 12) | ((ull)fj << F_SH)
                     | ((ull)(i + 1) << M_SH) | rvR;
            ull fjrec = (recd & ~(MMASK | RMASK))
                      | ((ull)(mp + 1) << M_SH) | rvR;

            // ---- query (uniform on ALL lanes; broadcast LDS, reads only) ----
            {
                int p = w, x = h;
                for (;;) {
                    if (p < 0) { p = 0; x = 0; break; }
                    ull r2 = S[p];
                    int tq = (int)((r2 >> qs) & IDA);
                    if (tq != IDA) { p = tq; x += 1; break; }
                    int mq = (int)((r2 >> M_SH) & IDA);
                    if (x > mq) x = mq;
                    int f = (int)((r2 >> F_SH) & IDA);
                    p = (f == IDA) ? -1 : f;
                }
                int y = 0;
                if (x > 0) {
                    ull recv = S[p];
                    for (;;) {
                        int f = (int)((recv >> F_SH) & IDA);
                        if (f == IDA) break;
                        ull recf = S[f];
                        if ((int)((recf >> M_SH) & IDA) >= x) recv = recf;
                        else break;
                    }
                    int idx = (int)(recv >> R_SH);        // r+1
                    y = (int)((vpk_s[idx >> 5] >> (idx & 31)) & 1u);
                }
                if (lane == 0) op[(size_t)i * CC] = y ? ev : -ev;
                w = p; h = x;
            }
            __syncwarp();   // S1: query reads complete

            // ---- single store phase (single writer per address) ----
            if (lane < s) {                                // plants (incl. g)
                ull pl = planted;
                if (donchain && lane == dlane) {
                    if (clone) pl = (pl & ~FMASK) | ((ull)bc << F_SH);  // f[d]=bc
                    else       pl = (pl & ~RMASK) | rvR;                // r[d]=rv
                }
                S[idt] = pl;
            }
            if (pres && lane == s) {
                if (clone) {
                    S[idt] = (rec & ~((ull)IDA << ks)) | ((ull)bc << ks);
                    S[bc]  = fjrec;
                    if (!donchain) S[d] = (recd & ~FMASK) | ((ull)bc << F_SH);
                } else if (!donchain) {
                    Sr[(d << 2) | 3] = rv;
                }
            }
            if (clone && inrun)
                S[idt] = (rec & ~((ull)IDA << ks)) | ((ull)bc << ks);
            if (lane == 0) {
                S[j] = jrec;
                NC[0] = (unsigned short)j;
                NC[1] = (unsigned short)fj;
                NC[Lnext - 1] = 0;                         // root terminal
            }
            if (keep) NC[pos] = (unsigned short)tgt;
            __syncwarp();   // S2: plants/clone visible

            if (validt && lane > s) Sr[(tgt << 2) | 3] = rv;  // r-propagation
            __syncwarp();   // S3: all writes visible to next step

            g = j; u += clone ? 2 : 1; L = Lnext;
            if (L > 32) degraded = true;   // S coherent; fallback takes over
        } else {
            // ---- serial fallback: lane 0, reference-style (always correct) ----
            if (lane == 0) {
                // query
                int p = w, x = h;
                for (;;) {
                    if (p < 0) { p = 0; x = 0; break; }
                    ull r2 = S[p];
                    int tq = (int)((r2 >> qs) & IDA);
                    if (tq != IDA) { p = tq; x += 1; break; }
                    int mq = (int)((r2 >> M_SH) & IDA);
                    if (x > mq) x = mq;
                    int f = (int)((r2 >> F_SH) & IDA);
                    p = (f == IDA) ? -1 : f;
                }
                int y = 0;
                if (x > 0) {
                    ull recv = S[p];
                    for (;;) {
                        int f = (int)((recv >> F_SH) & IDA);
                        if (f == IDA) break;
                        ull recf = S[f];
                        if ((int)((recf >> M_SH) & IDA) >= x) recv = recf;
                        else break;
                    }
                    int idx = (int)(recv >> R_SH);
                    y = (int)((vpk_s[idx >> 5] >> (idx & 31)) & 1u);
                }
                op[(size_t)i * CC] = y ? ev : -ev;
                w = p; h = x;
                // key
                int fj;
                int p2 = g;
                for (;;) {
                    if (p2 < 0) { fj = 0; break; }
                    ull t2r = S[p2];
                    int tk = (int)((t2r >> ks) & IDA);
                    if (tk == IDA) {
                        S[p2] = (t2r & ~((ull)IDA << ks)) | ((ull)j << ks);
                        int f = (int)((t2r >> F_SH) & IDA);
                        p2 = (f == IDA) ? -1 : f;
                    } else {
                        int d = tk;
                        ull recd = S[d];
                        int md = (int)((recd >> M_SH) & IDA);
                        int mp = (int)((t2r >> M_SH) & IDA);
                        if (mp + 1 == md) {
                            fj = d;
                        } else {
                            int bc = j + 1;
                            S[bc] = (recd & ~MMASK) | ((ull)(mp + 1) << M_SH);
                            S[d]  = (recd & ~FMASK) | ((ull)bc << F_SH);
                            fj = bc;
                            u += 1;
                            for (;;) {
                                ull t3 = S[p2];
                                if (((t3 >> ks) & IDA) != (ull)d) break;
                                S[p2] = (t3 & ~((ull)IDA << ks)) | ((ull)bc << ks);
                                int f = (int)((t3 >> F_SH) & IDA);
                                if (f == IDA) break;
                                p2 = f;
                            }
                        }
                        break;
                    }
                }
                int vst = fj;
                while (vst != 0) {
                    ull rc = S[vst];
                    Sr[(vst << 2) | 3] = rv;
                    int f = (int)((rc >> F_SH) & IDA);
                    if (f == IDA) break;
                    vst = f;
                }
                S[j] = (ull)IDA | ((ull)IDA << 12)
                     | ((ull)fj << F_SH)
                     | ((ull)(i + 1) << M_SH) | rvR;
                g = j;
                u += 1;
            }
            __syncwarp();
        }
    }
}

extern "C" void kernel_launch(void* const* d_in, const int* in_sizes, int n_in,
                              void* d_out, int out_size) {
    const float* q = (const float*)d_in[0];
    const float* k = (const float*)d_in[1];
    const float* v = (const float*)d_in[2];
    const float* e = (const float*)d_in[3];
    float* out = (float*)d_out;

    dim3 pg(WPB, BB);
    samx_pack_kernel<<<pg, CC>>>(q, k, v);

    size_t smem = (size_t)RPB * STATES * sizeof(ull)
                + (size_t)RPB * WPB * sizeof(uint32_t)
                + (size_t)RPB * CAPC * sizeof(unsigned short);  // 231644
    cudaFuncSetAttribute(samx_sam_kernel,
                         cudaFuncAttributeMaxDynamicSharedMemorySize, (int)smem);
    int blocks = (NROWS + RPB - 1) / RPB;                 // 147
    samx_sam_kernel<<<blocks, 32 * RPB, smem>>>(e, out);
}